// round 1
// baseline (speedup 1.0000x reference)
#include <cuda_runtime.h>

// Problem constants (fixed by the dataset):
//   x  [B=16384, D=1024] f32
//   Wh [T=512,  D=1024] f32
//   bh [T=512]          f32
//   Wb [1, D=1024]      f32
//   bb [1]              f32
//   out[B, T] = cumsum_t(relu(x @ Wh^T + bh)) + (x @ Wb^T + bb)

#define DDIM 1024
#define TDIM 512
#define BM   64
#define BN   512
#define BK   16
#define NTHREADS 512

// Dynamic smem layout (floats):
//   Wh_s  [BK][BN]   = 8192
//   x_s   [BK][BM]   = 1024
//   bh_s  [TDIM]     = 512
//   Wb_s  [BK]       = 16
//   base_s[BM]       = 64
//   haz_s [BM][TDIM] = 32768
#define SMEM_FLOATS (BK*BN + BK*BM + TDIM + BK + BM + BM*TDIM)
#define SMEM_BYTES  (SMEM_FLOATS * 4)

__global__ void __launch_bounds__(NTHREADS, 1)
surv_fused_kernel(const float* __restrict__ x,
                  const float* __restrict__ Wh,
                  const float* __restrict__ bh,
                  const float* __restrict__ Wb,
                  const float* __restrict__ bb,
                  float* __restrict__ out)
{
    extern __shared__ float smem[];
    float* Wh_s   = smem;                    // [BK][BN]
    float* x_s    = Wh_s + BK * BN;          // [BK][BM]
    float* bh_s   = x_s + BK * BM;           // [TDIM]
    float* Wb_s   = bh_s + TDIM;             // [BK]
    float* base_s = Wb_s + BK;               // [BM]
    float* haz_s  = base_s + BM;             // [BM][TDIM]

    const int tid  = threadIdx.x;
    const int ty   = tid >> 6;   // 0..7  (row group: rows ty*8 .. ty*8+7)
    const int tx   = tid & 63;   // 0..63 (col group: cols tx*4..+3 and 256+tx*4..+3)
    const int row0 = blockIdx.x * BM;

    // bh into smem (512 threads, 512 elements)
    bh_s[tid] = bh[tid];

    float acc[8][8];
    #pragma unroll
    for (int i = 0; i < 8; i++)
        #pragma unroll
        for (int j = 0; j < 8; j++) acc[i][j] = 0.f;
    float bacc[8];
    #pragma unroll
    for (int i = 0; i < 8; i++) bacc[i] = 0.f;

    const float* WhRow = Wh + (size_t)tid * DDIM;              // thread tid owns Wh row tid
    const float* xRow  = x + (size_t)(row0 + (tid & 63)) * DDIM; // threads 0..63 own x rows

    for (int k0 = 0; k0 < DDIM; k0 += BK) {
        __syncthreads();  // protect previous iteration's tile reads

        // --- load Wh tile: each thread loads its own T-row's 16 k-values,
        //     store transposed into Wh_s[kk][t] (conflict-free STS) ---
        float4 w0 = *(const float4*)(WhRow + k0 + 0);
        float4 w1 = *(const float4*)(WhRow + k0 + 4);
        float4 w2 = *(const float4*)(WhRow + k0 + 8);
        float4 w3 = *(const float4*)(WhRow + k0 + 12);
        Wh_s[ 0*BN + tid] = w0.x;  Wh_s[ 1*BN + tid] = w0.y;
        Wh_s[ 2*BN + tid] = w0.z;  Wh_s[ 3*BN + tid] = w0.w;
        Wh_s[ 4*BN + tid] = w1.x;  Wh_s[ 5*BN + tid] = w1.y;
        Wh_s[ 6*BN + tid] = w1.z;  Wh_s[ 7*BN + tid] = w1.w;
        Wh_s[ 8*BN + tid] = w2.x;  Wh_s[ 9*BN + tid] = w2.y;
        Wh_s[10*BN + tid] = w2.z;  Wh_s[11*BN + tid] = w2.w;
        Wh_s[12*BN + tid] = w3.x;  Wh_s[13*BN + tid] = w3.y;
        Wh_s[14*BN + tid] = w3.z;  Wh_s[15*BN + tid] = w3.w;

        // --- load x tile: threads 0..63 own one batch row each ---
        if (tid < BM) {
            float4 a0 = *(const float4*)(xRow + k0 + 0);
            float4 a1 = *(const float4*)(xRow + k0 + 4);
            float4 a2 = *(const float4*)(xRow + k0 + 8);
            float4 a3 = *(const float4*)(xRow + k0 + 12);
            x_s[ 0*BM + tid] = a0.x;  x_s[ 1*BM + tid] = a0.y;
            x_s[ 2*BM + tid] = a0.z;  x_s[ 3*BM + tid] = a0.w;
            x_s[ 4*BM + tid] = a1.x;  x_s[ 5*BM + tid] = a1.y;
            x_s[ 6*BM + tid] = a1.z;  x_s[ 7*BM + tid] = a1.w;
            x_s[ 8*BM + tid] = a2.x;  x_s[ 9*BM + tid] = a2.y;
            x_s[10*BM + tid] = a2.z;  x_s[11*BM + tid] = a2.w;
            x_s[12*BM + tid] = a3.x;  x_s[13*BM + tid] = a3.y;
            x_s[14*BM + tid] = a3.z;  x_s[15*BM + tid] = a3.w;
        }
        if (tid < BK) Wb_s[tid] = Wb[k0 + tid];

        __syncthreads();

        // --- compute: 8x8 micro-tile per thread ---
        #pragma unroll
        for (int kk = 0; kk < BK; kk++) {
            float a[8], b[8];
            *(float4*)(a + 0) = *(const float4*)(x_s + kk * BM + ty * 8);
            *(float4*)(a + 4) = *(const float4*)(x_s + kk * BM + ty * 8 + 4);
            *(float4*)(b + 0) = *(const float4*)(Wh_s + kk * BN + tx * 4);
            *(float4*)(b + 4) = *(const float4*)(Wh_s + kk * BN + 256 + tx * 4);
            #pragma unroll
            for (int i = 0; i < 8; i++)
                #pragma unroll
                for (int j = 0; j < 8; j++)
                    acc[i][j] = fmaf(a[i], b[j], acc[i][j]);
            if (tx == 0) {
                float wv = Wb_s[kk];
                #pragma unroll
                for (int i = 0; i < 8; i++) bacc[i] = fmaf(a[i], wv, bacc[i]);
            }
        }
    }

    __syncthreads();  // done with x_s/Wh_s; now stage hazards

    // --- relu(acc + bh) -> haz_s ---
    #pragma unroll
    for (int i = 0; i < 8; i++) {
        const int r = ty * 8 + i;
        float4 h0, h1;
        h0.x = fmaxf(acc[i][0] + bh_s[tx * 4 + 0], 0.f);
        h0.y = fmaxf(acc[i][1] + bh_s[tx * 4 + 1], 0.f);
        h0.z = fmaxf(acc[i][2] + bh_s[tx * 4 + 2], 0.f);
        h0.w = fmaxf(acc[i][3] + bh_s[tx * 4 + 3], 0.f);
        h1.x = fmaxf(acc[i][4] + bh_s[256 + tx * 4 + 0], 0.f);
        h1.y = fmaxf(acc[i][5] + bh_s[256 + tx * 4 + 1], 0.f);
        h1.z = fmaxf(acc[i][6] + bh_s[256 + tx * 4 + 2], 0.f);
        h1.w = fmaxf(acc[i][7] + bh_s[256 + tx * 4 + 3], 0.f);
        *(float4*)(haz_s + r * TDIM + tx * 4)       = h0;
        *(float4*)(haz_s + r * TDIM + 256 + tx * 4) = h1;
    }
    if (tx == 0) {
        float bbv = bb[0];
        #pragma unroll
        for (int i = 0; i < 8; i++) base_s[ty * 8 + i] = bacc[i] + bbv;
    }
    __syncthreads();

    // --- cumsum along T: one warp per row (16 warps, 64 rows -> 4 rows each) ---
    const int wid  = tid >> 5;
    const int lane = tid & 31;
    for (int r = wid; r < BM; r += 16) {
        float carry = 0.f;
        const float basev = base_s[r];
        const float* rowp = haz_s + r * TDIM;
        float* orow = out + (size_t)(row0 + r) * TDIM;
        #pragma unroll
        for (int c = 0; c < TDIM; c += 32) {
            float v = rowp[c + lane];
            #pragma unroll
            for (int off = 1; off < 32; off <<= 1) {
                float n = __shfl_up_sync(0xffffffffu, v, off);
                if (lane >= (unsigned)off) v += n;
            }
            orow[c + lane] = v + carry + basev;
            carry += __shfl_sync(0xffffffffu, v, 31);
        }
    }
}

extern "C" void kernel_launch(void* const* d_in, const int* in_sizes, int n_in,
                              void* d_out, int out_size)
{
    const float* x  = (const float*)d_in[0];
    const float* Wh = (const float*)d_in[1];
    const float* bh = (const float*)d_in[2];
    const float* Wb = (const float*)d_in[3];
    const float* bb = (const float*)d_in[4];
    float* out = (float*)d_out;

    (void)in_sizes; (void)n_in; (void)out_size;

    static bool attr_set = false;
    if (!attr_set) {
        cudaFuncSetAttribute(surv_fused_kernel,
                             cudaFuncAttributeMaxDynamicSharedMemorySize,
                             SMEM_BYTES);
        attr_set = true;
    }

    const int B = 16384;
    dim3 grid(B / BM);
    dim3 block(NTHREADS);
    surv_fused_kernel<<<grid, block, SMEM_BYTES>>>(x, Wh, bh, Wb, bb, out);
}

// round 3
// speedup vs baseline: 4.2724x; 4.2724x over previous
#include <cuda_runtime.h>
#include <cstdint>

// out[b,t] = cumsum_t( relu(x @ Wh^T + bh) ) + (x @ Wb^T + bb)
//   x [16384,1024] f32, Wh [512,1024] f32, bh[512], Wb[1,1024], bb[1]
//
// mma.sync tf32 (family-common ISA; tcgen05 is unavailable: harness PTX
// targets plain sm_103). CTA: 64 rows x N=512, K chunks of 32,
// 2-stage cp.async pipeline, padded smem rows (pitch 36) for
// conflict-free fragment LDS. Fused base GEMV + relu/bias + row cumsum.

#define DDIM   1024
#define TDIM   512
#define BROWS  16384
#define MTILE  64
#define KCHUNK 32
#define NCHUNKS 32
#define NTHREADS 512
#define XPITCH 36          // floats per smem row (32 data + 4 pad)
#define HPITCH 516         // hazards smem pitch

#define XS_F    (MTILE * XPITCH)        // 2304 floats
#define WS_F    (TDIM * XPITCH)         // 18432 floats
#define STAGE_F (XS_F + WS_F)           // 20736 floats
#define WB_OFF  (2 * STAGE_F)           // 41472
#define BH_OFF  (WB_OFF + DDIM)         // 42496
#define BASE_OFF (BH_OFF + TDIM)        // 43008
#define SMEM_F  (BASE_OFF + MTILE)      // 43072 floats
#define SMEM_BYTES (SMEM_F * 4)         // 172288 bytes

__device__ __forceinline__ uint32_t f2tf(float f) {
    uint32_t r;
    asm("cvt.rna.tf32.f32 %0, %1;" : "=r"(r) : "f"(f));
    return r;
}

__device__ __forceinline__ void mma_tf32(float* c, const uint32_t* a,
                                         uint32_t b0, uint32_t b1) {
    asm volatile(
        "mma.sync.aligned.m16n8k8.row.col.f32.tf32.tf32.f32 "
        "{%0,%1,%2,%3}, {%4,%5,%6,%7}, {%8,%9}, {%0,%1,%2,%3};"
        : "+f"(c[0]), "+f"(c[1]), "+f"(c[2]), "+f"(c[3])
        : "r"(a[0]), "r"(a[1]), "r"(a[2]), "r"(a[3]), "r"(b0), "r"(b1));
}

__device__ __forceinline__ void cp16(float* dst_s, const float* src_g) {
    uint32_t d = (uint32_t)__cvta_generic_to_shared(dst_s);
    asm volatile("cp.async.cg.shared.global [%0], [%1], 16;"
                 :: "r"(d), "l"(src_g));
}

__global__ void __launch_bounds__(NTHREADS, 1)
surv_mma_kernel(const float* __restrict__ x,
                const float* __restrict__ Wh,
                const float* __restrict__ bh,
                const float* __restrict__ Wb,
                const float* __restrict__ bb,
                float* __restrict__ out)
{
    extern __shared__ float sm[];
    float* wb_s   = sm + WB_OFF;
    float* bh_s   = sm + BH_OFF;
    float* base_s = sm + BASE_OFF;

    const int tid  = threadIdx.x;
    const int wid  = tid >> 5;
    const int lane = tid & 31;
    const int mw   = wid & 1;        // 2 M-warps (32 rows each)
    const int nw   = wid >> 1;       // 8 N-warps (64 cols each)
    const int l4   = lane >> 2;      // 0..7
    const int lk   = lane & 3;       // 0..3
    const int row0 = blockIdx.x * MTILE;

    // ---- cp.async tile issue ----
    auto issue = [&](int chunk, int buf) {
        const int kb = chunk * KCHUNK;
        float* xs = sm + buf * STAGE_F;
        float* ws = xs + XS_F;
        const int rb = tid >> 3;     // 0..63
        const int sg = tid & 7;      // 16B segment
        cp16(xs + rb * XPITCH + sg * 4,
             x + (size_t)(row0 + rb) * DDIM + kb + sg * 4);
        #pragma unroll
        for (int i = 0; i < 8; i++) {
            const int rown = rb + 64 * i;
            cp16(ws + rown * XPITCH + sg * 4,
                 Wh + (size_t)rown * DDIM + kb + sg * 4);
        }
    };

    float acc[2][8][4];
    #pragma unroll
    for (int i = 0; i < 2; i++)
        #pragma unroll
        for (int j = 0; j < 8; j++)
            #pragma unroll
            for (int q = 0; q < 4; q++) acc[i][j][q] = 0.f;
    float bacc = 0.f;

    issue(0, 0); asm volatile("cp.async.commit_group;" ::: "memory");
    issue(1, 1); asm volatile("cp.async.commit_group;" ::: "memory");

    // preload Wb (1024) + bh (512)
    wb_s[tid]       = Wb[tid];
    wb_s[tid + 512] = Wb[tid + 512];
    bh_s[tid & 511] = bh[tid & 511];

    for (int c = 0; c < NCHUNKS; c++) {
        if (c < NCHUNKS - 1) asm volatile("cp.async.wait_group 1;" ::: "memory");
        else                 asm volatile("cp.async.wait_group 0;" ::: "memory");
        __syncthreads();

        const float* xs = sm + (c & 1) * STAGE_F;
        const float* ws = xs + XS_F;

        // base GEMV: warp wid covers rows 4*wid..4*wid+3, 8 lanes per row
        {
            const int rowb = (wid << 2) + (lane >> 3);
            const int ko   = (lane & 7) * 4;
            float4 xv = *(const float4*)(xs + rowb * XPITCH + ko);
            float4 wv = *(const float4*)(wb_s + c * KCHUNK + ko);
            bacc = fmaf(xv.x, wv.x, bacc);
            bacc = fmaf(xv.y, wv.y, bacc);
            bacc = fmaf(xv.z, wv.z, bacc);
            bacc = fmaf(xv.w, wv.w, bacc);
        }

        const float* xa = xs + (mw * 32 + l4) * XPITCH + lk;
        const float* wp = ws + (nw * 64 + l4) * XPITCH + lk;

        #pragma unroll
        for (int ks = 0; ks < 4; ks++) {
            const int o = ks * 8;
            uint32_t a[8];
            a[0] = f2tf(xa[o]);
            a[1] = f2tf(xa[o + 8 * XPITCH]);
            a[2] = f2tf(xa[o + 4]);
            a[3] = f2tf(xa[o + 8 * XPITCH + 4]);
            a[4] = f2tf(xa[o + 16 * XPITCH]);
            a[5] = f2tf(xa[o + 24 * XPITCH]);
            a[6] = f2tf(xa[o + 16 * XPITCH + 4]);
            a[7] = f2tf(xa[o + 24 * XPITCH + 4]);
            #pragma unroll
            for (int j = 0; j < 8; j++) {
                uint32_t b0 = f2tf(wp[j * 8 * XPITCH + o]);
                uint32_t b1 = f2tf(wp[j * 8 * XPITCH + o + 4]);
                mma_tf32(acc[0][j], a,     b0, b1);
                mma_tf32(acc[1][j], a + 4, b0, b1);
            }
        }
        __syncthreads();
        if (c + 2 < NCHUNKS) {
            issue(c + 2, c & 1);
            asm volatile("cp.async.commit_group;" ::: "memory");
        }
    }

    // ---- base reduction: sum 8 lanes per row ----
    bacc += __shfl_down_sync(0xffffffffu, bacc, 4, 8);
    bacc += __shfl_down_sync(0xffffffffu, bacc, 2, 8);
    bacc += __shfl_down_sync(0xffffffffu, bacc, 1, 8);
    if ((lane & 7) == 0) base_s[(wid << 2) + (lane >> 3)] = bacc;

    // ---- hazards: relu(acc + bh) -> smem (reuse stage buffers) ----
    float* haz = sm;
    const int r0 = mw * 32 + l4;
    const int cb = nw * 64 + 2 * lk;
    #pragma unroll
    for (int i = 0; i < 2; i++) {
        #pragma unroll
        for (int j = 0; j < 8; j++) {
            const int cc = cb + 8 * j;
            const int rA = r0 + 16 * i;
            const float bhc0 = bh_s[cc], bhc1 = bh_s[cc + 1];
            float2 vA, vB;
            vA.x = fmaxf(acc[i][j][0] + bhc0, 0.f);
            vA.y = fmaxf(acc[i][j][1] + bhc1, 0.f);
            vB.x = fmaxf(acc[i][j][2] + bhc0, 0.f);
            vB.y = fmaxf(acc[i][j][3] + bhc1, 0.f);
            *(float2*)(haz + rA * HPITCH + cc)       = vA;
            *(float2*)(haz + (rA + 8) * HPITCH + cc) = vB;
        }
    }
    __syncthreads();

    // ---- per-row inclusive cumsum + base, store ----
    const float bbv = bb[0];
    for (int r = wid; r < MTILE; r += 16) {
        float carry = base_s[r] + bbv;
        const float* rowp = haz + r * HPITCH;
        float* orow = out + (size_t)(row0 + r) * TDIM;
        #pragma unroll
        for (int cc = 0; cc < TDIM; cc += 32) {
            float v = rowp[cc + lane];
            #pragma unroll
            for (int off = 1; off < 32; off <<= 1) {
                float n = __shfl_up_sync(0xffffffffu, v, off);
                if (lane >= (unsigned)off) v += n;
            }
            orow[cc + lane] = v + carry;
            carry += __shfl_sync(0xffffffffu, v, 31);
        }
    }
}

extern "C" void kernel_launch(void* const* d_in, const int* in_sizes, int n_in,
                              void* d_out, int out_size)
{
    const float* x  = (const float*)d_in[0];
    const float* Wh = (const float*)d_in[1];
    const float* bh = (const float*)d_in[2];
    const float* Wb = (const float*)d_in[3];
    const float* bb = (const float*)d_in[4];
    float* out = (float*)d_out;
    (void)in_sizes; (void)n_in; (void)out_size;

    static bool attr_set = false;
    if (!attr_set) {
        cudaFuncSetAttribute(surv_mma_kernel,
                             cudaFuncAttributeMaxDynamicSharedMemorySize,
                             SMEM_BYTES);
        attr_set = true;
    }

    dim3 grid(BROWS / MTILE);   // 256
    dim3 block(NTHREADS);
    surv_mma_kernel<<<grid, block, SMEM_BYTES>>>(x, Wh, bh, Wb, bb, out);
}

// round 4
// speedup vs baseline: 4.2823x; 1.0023x over previous
#include <cuda_runtime.h>
#include <cstdint>

// out[b,t] = cumsum_t( relu(x @ Wh^T + bh) ) + (x @ Wb^T + bb)
//   x [16384,1024] f32, Wh [512,1024] f32, bh[512], Wb[1,1024], bb[1]
//
// mma.sync tf32 (family-common ISA). 8 warps, CTA 64x512, warp tile 64x64.
// Wh pre-rounded to tf32 and k-permuted into __device__ scratch (prepass).
// x rounded+permuted per-chunk in smem. k-permutation makes fragment loads
// LDS.128. In-register epilogue: relu+bias, 4-lane segmented scan,
// cross-warp segment prefix, fused base GEMV.

#define DDIM   1024
#define TDIM   512
#define BROWS  16384
#define MTILE  64
#define KCHUNK 32
#define NCHUNKS 32
#define NTHREADS 256
#define P      36                 // ws/xt pitch in words

// smem offsets (floats)
#define WS0   0
#define WS1   18432               // 512*36
#define XR0   36864               // x raw, pitch 32
#define XR1   38912
#define XT0   40960               // x tf32 permuted, pitch 36
#define XT1   43264
#define WB_O  45568
#define BH_O  46592
#define BASE_O 47104
#define SEG_O 47168
#define SMEM_F 47680
#define SMEM_BYTES (SMEM_F * 4)   // 190720

__device__ float g_whs[TDIM * DDIM];   // pre-rounded, k-permuted Wh

__device__ __forceinline__ uint32_t f2tf(float f) {
    uint32_t r;
    asm("cvt.rna.tf32.f32 %0, %1;" : "=r"(r) : "f"(f));
    return r;
}
__device__ __forceinline__ void mma_tf32(float* c, uint32_t a0, uint32_t a1,
                                         uint32_t a2, uint32_t a3,
                                         uint32_t b0, uint32_t b1) {
    asm volatile(
        "mma.sync.aligned.m16n8k8.row.col.f32.tf32.tf32.f32 "
        "{%0,%1,%2,%3}, {%4,%5,%6,%7}, {%8,%9}, {%0,%1,%2,%3};"
        : "+f"(c[0]), "+f"(c[1]), "+f"(c[2]), "+f"(c[3])
        : "r"(a0), "r"(a1), "r"(a2), "r"(a3), "r"(b0), "r"(b1));
}
__device__ __forceinline__ void cp16(float* dst_s, const float* src_g) {
    uint32_t d = (uint32_t)__cvta_generic_to_shared(dst_s);
    asm volatile("cp.async.cg.shared.global [%0], [%1], 16;" :: "r"(d), "l"(src_g));
}

// prepass: round Wh to tf32 (RN) and store k-permuted:
//   within each 32-k chunk: phys = 8*(j&3) + 2*s + (j>>2), k = 32*c + 8*s + j
__global__ void __launch_bounds__(256) prep_wh_kernel(const float* __restrict__ Wh) {
    const int row = blockIdx.x;
    const int k4  = threadIdx.x * 4;
    float4 v = *(const float4*)(Wh + (size_t)row * DDIM + k4);
    #pragma unroll
    for (int e = 0; e < 4; e++) {
        int k = k4 + e;
        int c = k >> 5, k5 = k & 31, s = k5 >> 3, j = k5 & 7;
        int phys = c * 32 + 8 * (j & 3) + 2 * s + (j >> 2);
        uint32_t t = f2tf(((const float*)&v)[e]);
        g_whs[(size_t)row * DDIM + phys] = __uint_as_float(t);
    }
}

__global__ void __launch_bounds__(NTHREADS, 1)
surv_mma8_kernel(const float* __restrict__ x,
                 const float* __restrict__ bh,
                 const float* __restrict__ Wb,
                 const float* __restrict__ bb,
                 float* __restrict__ out)
{
    extern __shared__ float sm[];
    float* wb_s   = sm + WB_O;
    float* bh_s   = sm + BH_O;
    float* base_s = sm + BASE_O;
    float* seg_s  = sm + SEG_O;

    const int tid  = threadIdx.x;
    const int wid  = tid >> 5;        // 0..7 : N segment (64 cols)
    const int lane = tid & 31;
    const int l4   = lane >> 2;
    const int lk   = lane & 3;
    const int row0 = blockIdx.x * MTILE;

    auto issue = [&](int c, int buf) {
        float* ws = sm + (buf ? WS1 : WS0);
        float* xr = sm + (buf ? XR1 : XR0);
        const int seg = tid & 7;
        const int rb  = tid >> 3;
        #pragma unroll
        for (int i = 0; i < 16; i++) {
            const int r = rb + 32 * i;
            cp16(ws + r * P + seg * 4,
                 g_whs + (size_t)r * DDIM + c * KCHUNK + seg * 4);
        }
        #pragma unroll
        for (int i = 0; i < 2; i++) {
            const int r = rb + 32 * i;
            cp16(xr + r * 32 + seg * 4,
                 x + (size_t)(row0 + r) * DDIM + c * KCHUNK + seg * 4);
        }
    };

    float acc[4][8][4];
    #pragma unroll
    for (int i = 0; i < 4; i++)
        #pragma unroll
        for (int j = 0; j < 8; j++)
            #pragma unroll
            for (int q = 0; q < 4; q++) acc[i][j][q] = 0.f;
    float bacc = 0.f;

    issue(0, 0); asm volatile("cp.async.commit_group;" ::: "memory");
    issue(1, 1); asm volatile("cp.async.commit_group;" ::: "memory");

    // preload Wb (1024) + bh (512)
    #pragma unroll
    for (int i = 0; i < 4; i++) wb_s[tid + 256 * i] = Wb[tid + 256 * i];
    bh_s[tid] = bh[tid];
    bh_s[tid + 256] = bh[tid + 256];

    const int rr = tid >> 2;          // 0..63 (convert + base row)
    const int s4 = tid & 3;

    for (int c = 0; c < NCHUNKS; c++) {
        if (c < NCHUNKS - 1) asm volatile("cp.async.wait_group 1;" ::: "memory");
        else                 asm volatile("cp.async.wait_group 0;" ::: "memory");
        __syncthreads();

        const int buf = c & 1;
        float* ws = sm + (buf ? WS1 : WS0);
        float* xr = sm + (buf ? XR1 : XR0);
        float* xt = sm + (buf ? XT1 : XT0);

        // ---- convert x tile: round RN + permute (8 elems/thread) ----
        float4 xv0 = *(const float4*)(xr + rr * 32 + s4 * 8);
        float4 xv1 = *(const float4*)(xr + rr * 32 + s4 * 8 + 4);
        {
            const float* vv0 = (const float*)&xv0;
            const float* vv1 = (const float*)&xv1;
            #pragma unroll
            for (int j = 0; j < 8; j++) {
                float f = (j < 4) ? vv0[j] : vv1[j - 4];
                int phys = 8 * (j & 3) + 2 * s4 + (j >> 2);
                xt[rr * P + phys] = __uint_as_float(f2tf(f));
            }
        }
        // ---- base GEMV partial (exact fp32, from raw x) ----
        {
            float4 wv0 = *(const float4*)(wb_s + c * KCHUNK + s4 * 8);
            float4 wv1 = *(const float4*)(wb_s + c * KCHUNK + s4 * 8 + 4);
            bacc = fmaf(xv0.x, wv0.x, bacc); bacc = fmaf(xv0.y, wv0.y, bacc);
            bacc = fmaf(xv0.z, wv0.z, bacc); bacc = fmaf(xv0.w, wv0.w, bacc);
            bacc = fmaf(xv1.x, wv1.x, bacc); bacc = fmaf(xv1.y, wv1.y, bacc);
            bacc = fmaf(xv1.z, wv1.z, bacc); bacc = fmaf(xv1.w, wv1.w, bacc);
        }
        __syncthreads();   // xt ready

        // ---- MMA: warp tile 64x64, LDS.128 fragments ----
        #pragma unroll
        for (int sp = 0; sp < 2; sp++) {
            uint4 af[4][2], bf[8];
            #pragma unroll
            for (int i = 0; i < 4; i++) {
                af[i][0] = *(const uint4*)(xt + (16 * i + l4) * P + 8 * lk + 4 * sp);
                af[i][1] = *(const uint4*)(xt + (16 * i + 8 + l4) * P + 8 * lk + 4 * sp);
            }
            #pragma unroll
            for (int j = 0; j < 8; j++)
                bf[j] = *(const uint4*)(ws + (wid * 64 + 8 * j + l4) * P + 8 * lk + 4 * sp);
            #pragma unroll
            for (int s2 = 0; s2 < 2; s2++) {
                #pragma unroll
                for (int i = 0; i < 4; i++) {
                    uint32_t a0 = s2 ? af[i][0].z : af[i][0].x;
                    uint32_t a2 = s2 ? af[i][0].w : af[i][0].y;
                    uint32_t a1 = s2 ? af[i][1].z : af[i][1].x;
                    uint32_t a3 = s2 ? af[i][1].w : af[i][1].y;
                    #pragma unroll
                    for (int j = 0; j < 8; j++) {
                        uint32_t b0 = s2 ? bf[j].z : bf[j].x;
                        uint32_t b1 = s2 ? bf[j].w : bf[j].y;
                        mma_tf32(acc[i][j], a0, a1, a2, a3, b0, b1);
                    }
                }
            }
        }
        __syncthreads();   // stage reads done
        if (c + 2 < NCHUNKS) {
            issue(c + 2, buf);
            asm volatile("cp.async.commit_group;" ::: "memory");
        }
    }

    // ---- base reduce: 4 lanes per row ----
    bacc += __shfl_down_sync(0xffffffffu, bacc, 2, 4);
    bacc += __shfl_down_sync(0xffffffffu, bacc, 1, 4);
    if ((tid & 3) == 0) base_s[rr] = bacc;

    // ---- per-row segmented scan (64 cols per warp) ----
    float2 bhv[8];
    #pragma unroll
    for (int j = 0; j < 8; j++)
        bhv[j] = *(const float2*)(bh_s + wid * 64 + 8 * j + 2 * lk);

    #pragma unroll
    for (int i = 0; i < 4; i++) {
        #pragma unroll
        for (int hh = 0; hh < 2; hh++) {
            const int row = 16 * i + 8 * hh + l4;
            float carry = 0.f;
            #pragma unroll
            for (int j = 0; j < 8; j++) {
                float v0 = fmaxf(acc[i][j][2 * hh]     + bhv[j].x, 0.f);
                float v1 = fmaxf(acc[i][j][2 * hh + 1] + bhv[j].y, 0.f);
                float p = v0 + v1;
                float incl = p, t;
                t = __shfl_up_sync(0xffffffffu, incl, 1, 4); if (lk >= 1) incl += t;
                t = __shfl_up_sync(0xffffffffu, incl, 2, 4); if (lk >= 2) incl += t;
                float excl = incl - p;
                acc[i][j][2 * hh]     = carry + excl + v0;
                acc[i][j][2 * hh + 1] = carry + incl;
                carry += __shfl_sync(0xffffffffu, incl, 3, 4);
            }
            if (lk == 0) seg_s[row * 8 + wid] = carry;
        }
    }
    __syncthreads();

    // ---- cross-warp segment prefix + base, store ----
    const float bbv = bb[0];
    #pragma unroll
    for (int i = 0; i < 4; i++) {
        #pragma unroll
        for (int hh = 0; hh < 2; hh++) {
            const int row = 16 * i + 8 * hh + l4;
            float g = base_s[row] + bbv;
            #pragma unroll
            for (int s = 0; s < 8; s++)
                if (s < wid) g += seg_s[row * 8 + s];
            float* orow = out + (size_t)(row0 + row) * TDIM + wid * 64 + 2 * lk;
            #pragma unroll
            for (int j = 0; j < 8; j++) {
                float2 o;
                o.x = acc[i][j][2 * hh]     + g;
                o.y = acc[i][j][2 * hh + 1] + g;
                *(float2*)(orow + 8 * j) = o;
            }
        }
    }
}

extern "C" void kernel_launch(void* const* d_in, const int* in_sizes, int n_in,
                              void* d_out, int out_size)
{
    const float* x  = (const float*)d_in[0];
    const float* Wh = (const float*)d_in[1];
    const float* bh = (const float*)d_in[2];
    const float* Wb = (const float*)d_in[3];
    const float* bb = (const float*)d_in[4];
    float* out = (float*)d_out;
    (void)in_sizes; (void)n_in; (void)out_size;

    static bool attr_set = false;
    if (!attr_set) {
        cudaFuncSetAttribute(surv_mma8_kernel,
                             cudaFuncAttributeMaxDynamicSharedMemorySize,
                             SMEM_BYTES);
        attr_set = true;
    }

    prep_wh_kernel<<<TDIM, 256>>>(Wh);
    surv_mma8_kernel<<<BROWS / MTILE, NTHREADS, SMEM_BYTES>>>(x, bh, Wb, bb, out);
}